// round 11
// baseline (speedup 1.0000x reference)
#include <cuda_runtime.h>
#include <cstdint>

// ---------------------------------------------------------------------------
// out[8192,1000] = sign(X) @ sign(W)^T via bit-packing + XOR+POPC.
// dot = D - 2*popc(a^b). Key op-mix decision (R9 post-mortem): GEMM is
// alu-issue-bound; POPC and XOR share the full-rate alu pipe. So the
// accumulate is forced onto the *fma* pipe via IMAD (acc += p * one, with
// `one` an opaque kernel arg) -> alu cost drops to 2.0 inst/word.
// cp.async double-buffered K-chunks overlap global loads with compute.
// ---------------------------------------------------------------------------
#define M_DIM 8192
#define N_DIM 1000
#define NP    1024
#define D_DIM 12288
#define KW    384            // 32-bit words per row
#define KCW   32             // words per K-chunk
#define NCH   12             // KW / KCW
#define RSB   144            // smem row stride bytes (36 words, conflict-free)
#define TILE_B   (128 * RSB)            // 18432 B per operand tile
#define STAGE_B  (2 * TILE_B)           // 36864 B (A + B)
#define SMEM_REQ (2 * STAGE_B)          // 73728 B (2 stages) -> 2 CTAs/SM

__device__ uint32_t g_bitsA[(size_t)M_DIM * KW];   // 12.6 MB
__device__ uint32_t g_bitsW[(size_t)NP * KW];      // 1.6 MB (pad rows zero)

// ============================ helpers ======================================
__device__ __forceinline__ uint32_t smem_to_u32(const void* p) {
    uint32_t a;
    asm("{ .reg .u64 t; cvta.to.shared.u64 t, %1; cvt.u32.u64 %0, t; }"
        : "=r"(a) : "l"(p));
    return a;
}
__device__ __forceinline__ void cp_async16(uint32_t saddr, const void* gptr) {
    asm volatile("cp.async.cg.shared.global [%0], [%1], 16;"
                 :: "r"(saddr), "l"(gptr));
}
#define CP_COMMIT() asm volatile("cp.async.commit_group;" ::: "memory")
#define CP_WAIT(n)  asm volatile("cp.async.wait_group %0;" :: "n"(n) : "memory")

// =========================== pack kernels ==================================
__global__ __launch_bounds__(256)
void pack_sign_A(const float* __restrict__ in, uint32_t* __restrict__ out,
                 int nwords) {
    int warp_id = (blockIdx.x * blockDim.x + threadIdx.x) >> 5;
    int lane    = threadIdx.x & 31;
    int w0 = warp_id * 4;
    if (w0 >= nwords) return;
    const float* base = in + (size_t)w0 * 32;
    uint32_t w[4];
#pragma unroll
    for (int c = 0; c < 4; c++)
        w[c] = __ballot_sync(0xffffffffu, base[c * 32 + lane] > 0.0f);
    if (lane == 0)
        *reinterpret_cast<uint4*>(out + w0) = make_uint4(w[0], w[1], w[2], w[3]);
}

__global__ __launch_bounds__(256)
void pack_sign_W(const float* __restrict__ in, uint32_t* __restrict__ out) {
    int warp_id = (blockIdx.x * blockDim.x + threadIdx.x) >> 5;
    int lane    = threadIdx.x & 31;
    int w0 = warp_id * 4;                  // KW % 4 == 0 -> stays in one row
    if (w0 >= NP * KW) return;
    int row = w0 / KW;
    uint32_t w[4] = {0u, 0u, 0u, 0u};
    if (row < N_DIM) {
        const float* base = in + (size_t)w0 * 32;
#pragma unroll
        for (int c = 0; c < 4; c++)
            w[c] = __ballot_sync(0xffffffffu, base[c * 32 + lane] > 0.0f);
    }
    if (lane == 0)
        *reinterpret_cast<uint4*>(out + w0) = make_uint4(w[0], w[1], w[2], w[3]);
}

// ============================== GEMM =======================================
// 128x128 tile, 256 threads, 8x8 micro-tile (R2 structure, proven fastest).
__global__ __launch_bounds__(256, 2)
void bgemm_popc_kernel(const uint32_t* __restrict__ Ab,
                       const uint32_t* __restrict__ Wb,
                       float* __restrict__ out,
                       const int one /* runtime 1: forces IMAD accumulate */)
{
    extern __shared__ char smem[];
    const uint32_t sbase = smem_to_u32(smem);
    const int tid = threadIdx.x;
    const int tx  = tid & 15;
    const int ty  = tid >> 4;
    const int mBase = blockIdx.y * 128;
    const int nBase = blockIdx.x * 128;

    int acc[8][8];
#pragma unroll
    for (int i = 0; i < 8; i++)
#pragma unroll
        for (int j = 0; j < 8; j++) acc[i][j] = 0;

    // --- stage loader: A/B 128 rows x 32 words, 16B cp.async units ---------
    auto load_stage = [&](int stage, int chunk) {
        const uint32_t sA = sbase + stage * STAGE_B;
        const uint32_t sB = sA + TILE_B;
        const int kw = chunk * KCW;
#pragma unroll
        for (int l = 0; l < 4; l++) {           // 1024 units each, 4/thread
            int u = tid + l * 256;
            int row = u >> 3, c = u & 7;
            uint32_t d = (uint32_t)(row * RSB + c * 16);
            cp_async16(sA + d, Ab + (size_t)(mBase + row) * KW + kw + c * 4);
            cp_async16(sB + d, Wb + (size_t)(nBase + row) * KW + kw + c * 4);
        }
    };

    // --- compute one 32-word chunk ------------------------------------------
    auto compute_stage = [&](int stage) {
        const char* cA = smem + stage * STAGE_B;
        const char* cB = cA + TILE_B;
#pragma unroll
        for (int k = 0; k < KCW; k += 4) {
            uint4 b4[8];
#pragma unroll
            for (int j = 0; j < 8; j++)
                b4[j] = *reinterpret_cast<const uint4*>(
                    cB + (tx + 16 * j) * RSB + k * 4);
#pragma unroll
            for (int i = 0; i < 8; i++) {
                uint4 a4 = *reinterpret_cast<const uint4*>(
                    cA + (ty + 16 * i) * RSB + k * 4);
#pragma unroll
                for (int j = 0; j < 8; j++) {
                    // XOR (alu) + POPC (alu) + IMAD (fma; `one` is opaque)
                    acc[i][j] += __popc(a4.x ^ b4[j].x) * one;
                    acc[i][j] += __popc(a4.y ^ b4[j].y) * one;
                    acc[i][j] += __popc(a4.z ^ b4[j].z) * one;
                    acc[i][j] += __popc(a4.w ^ b4[j].w) * one;
                }
            }
        }
    };

    // --- 2-stage cp.async pipeline ------------------------------------------
    load_stage(0, 0); CP_COMMIT();
    for (int i = 0; i < NCH; i++) {
        if (i + 1 < NCH) load_stage((i + 1) & 1, i + 1);
        CP_COMMIT();
        CP_WAIT(1);
        __syncthreads();
        compute_stage(i & 1);
        __syncthreads();      // protect buffer (i&1) before it is reloaded
    }

    // --- epilogue: dot = D - 2*mismatches; pad columns masked ---------------
#pragma unroll
    for (int i = 0; i < 8; i++) {
        int m = mBase + ty + 16 * i;
#pragma unroll
        for (int j = 0; j < 8; j++) {
            int n = nBase + tx + 16 * j;
            if (n < N_DIM)
                out[(size_t)m * N_DIM + n] = (float)(D_DIM - 2 * acc[i][j]);
        }
    }
}

// =============================== launcher ==================================
extern "C" void kernel_launch(void* const* d_in, const int* in_sizes, int n_in,
                              void* d_out, int out_size) {
    const float* inp = (const float*)d_in[0];   // [8192, 12288]
    const float* wt  = (const float*)d_in[1];   // [1000, 12288]
    float* out = (float*)d_out;                 // [8192, 1000]

    uint32_t* bitsA = nullptr;
    uint32_t* bitsW = nullptr;
    cudaGetSymbolAddress((void**)&bitsA, g_bitsA);
    cudaGetSymbolAddress((void**)&bitsW, g_bitsW);

    {   // pack A (BW-bound, ~80us)
        int nwords = M_DIM * KW;
        int blocks = (nwords / 4 * 32 + 255) / 256;
        pack_sign_A<<<blocks, 256>>>(inp, bitsA, nwords);
    }
    {   // pack W padded to 1024 rows
        int nwords = NP * KW;
        int blocks = (nwords / 4 * 32 + 255) / 256;
        pack_sign_W<<<blocks, 256>>>(wt, bitsW);
    }

    static bool attr_set = false;
    if (!attr_set) {
        cudaFuncSetAttribute(bgemm_popc_kernel,
                             cudaFuncAttributeMaxDynamicSharedMemorySize, SMEM_REQ);
        attr_set = true;
    }
    // opaque 1: derived from a runtime value the compiler cannot fold
    int one = (n_in >= 1) ? 1 : 2;
    dim3 grid(NP / 128, M_DIM / 128);   // x = N tiles (A-tile L2 reuse), y = M
    bgemm_popc_kernel<<<grid, 256, SMEM_REQ>>>(bitsA, bitsW, out, one);
}

// round 12
// speedup vs baseline: 1.6256x; 1.6256x over previous
#include <cuda_runtime.h>
#include <cstdint>

// ---------------------------------------------------------------------------
// out[8192,1000] = sign(X) @ sign(W)^T via bit-packing + XOR+POPC.
// dot = D - 2*popc(a^b). R11 post-mortem: R2's plain popc-sum formulation
// (XOR + POPC + IADD3-tree, ~2.5 alu inst/word) is the op-mix optimum; CSA
// and IMAD variants both regressed. This round keeps that loop EXACTLY and
// adds only a cp.async double-buffer (load/compute overlap) + a higher-MLP
// pack kernel.
// ---------------------------------------------------------------------------
#define M_DIM 8192
#define N_DIM 1000
#define NP    1024
#define D_DIM 12288
#define KW    384            // 32-bit words per row
#define KCW   32             // words per K-chunk
#define NCH   12             // KW / KCW
#define RSB   144            // smem row stride bytes (36 words, conflict-free)
#define TILE_B   (128 * RSB)            // 18432 B per operand tile
#define STAGE_B  (2 * TILE_B)           // 36864 B (A + B)
#define SMEM_REQ (2 * STAGE_B)          // 73728 B (2 stages) -> 2 CTAs/SM

__device__ uint32_t g_bitsA[(size_t)M_DIM * KW];   // 12.6 MB
__device__ uint32_t g_bitsW[(size_t)NP * KW];      // 1.6 MB (pad rows zero)

// ============================ helpers ======================================
__device__ __forceinline__ uint32_t smem_to_u32(const void* p) {
    uint32_t a;
    asm("{ .reg .u64 t; cvta.to.shared.u64 t, %1; cvt.u32.u64 %0, t; }"
        : "=r"(a) : "l"(p));
    return a;
}
__device__ __forceinline__ void cp_async16(uint32_t saddr, const void* gptr) {
    asm volatile("cp.async.cg.shared.global [%0], [%1], 16;"
                 :: "r"(saddr), "l"(gptr));
}
#define CP_COMMIT() asm volatile("cp.async.commit_group;" ::: "memory")
#define CP_WAIT(n)  asm volatile("cp.async.wait_group %0;" :: "n"(n) : "memory")

// =========================== pack kernels ==================================
// Each warp packs 16 words (512 floats) per iteration: 16 independent 128B
// coalesced loads in flight (MLP=16) before the ballot chain, then lanes 0-3
// store one uint4 each.
__global__ __launch_bounds__(256)
void pack_sign_A(const float* __restrict__ in, uint32_t* __restrict__ out,
                 int nwords) {
    int warp_id = (blockIdx.x * blockDim.x + threadIdx.x) >> 5;
    int lane    = threadIdx.x & 31;
    int w0 = warp_id * 16;
    if (w0 >= nwords) return;
    const float* base = in + (size_t)w0 * 32 + lane;
    float v[16];
#pragma unroll
    for (int c = 0; c < 16; c++) v[c] = base[c * 32];   // 16 loads in flight
    uint32_t w[16];
#pragma unroll
    for (int c = 0; c < 16; c++)
        w[c] = __ballot_sync(0xffffffffu, v[c] > 0.0f);
    if (lane < 4) {
        *reinterpret_cast<uint4*>(out + w0 + lane * 4) =
            make_uint4(w[lane * 4], w[lane * 4 + 1],
                       w[lane * 4 + 2], w[lane * 4 + 3]);
    }
}

// W packed into NP=1024 rows; rows >= N_DIM zero. Small (~11us), keep simple.
__global__ __launch_bounds__(256)
void pack_sign_W(const float* __restrict__ in, uint32_t* __restrict__ out) {
    int warp_id = (blockIdx.x * blockDim.x + threadIdx.x) >> 5;
    int lane    = threadIdx.x & 31;
    int w0 = warp_id * 4;                  // KW % 4 == 0 -> stays in one row
    if (w0 >= NP * KW) return;
    int row = w0 / KW;
    uint32_t w[4] = {0u, 0u, 0u, 0u};
    if (row < N_DIM) {
        const float* base = in + (size_t)w0 * 32;
#pragma unroll
        for (int c = 0; c < 4; c++)
            w[c] = __ballot_sync(0xffffffffu, base[c * 32 + lane] > 0.0f);
    }
    if (lane == 0)
        *reinterpret_cast<uint4*>(out + w0) = make_uint4(w[0], w[1], w[2], w[3]);
}

// ============================== GEMM =======================================
// 128x128 tile, 256 threads, 8x8 micro-tile — R2's exact compute loop.
__global__ __launch_bounds__(256, 2)
void bgemm_popc_kernel(const uint32_t* __restrict__ Ab,
                       const uint32_t* __restrict__ Wb,
                       float* __restrict__ out)
{
    extern __shared__ char smem[];
    const uint32_t sbase = smem_to_u32(smem);
    const int tid = threadIdx.x;
    const int tx  = tid & 15;
    const int ty  = tid >> 4;
    const int mBase = blockIdx.y * 128;
    const int nBase = blockIdx.x * 128;

    int acc[8][8];
#pragma unroll
    for (int i = 0; i < 8; i++)
#pragma unroll
        for (int j = 0; j < 8; j++) acc[i][j] = 0;

    // --- stage loader: A/B 128 rows x 32 words, 16B cp.async units ---------
    auto load_stage = [&](int stage, int chunk) {
        const uint32_t sA = sbase + stage * STAGE_B;
        const uint32_t sB = sA + TILE_B;
        const int kw = chunk * KCW;
#pragma unroll
        for (int l = 0; l < 4; l++) {           // 1024 units each, 4/thread
            int u = tid + l * 256;
            int row = u >> 3, c = u & 7;
            uint32_t d = (uint32_t)(row * RSB + c * 16);
            cp_async16(sA + d, Ab + (size_t)(mBase + row) * KW + kw + c * 4);
            cp_async16(sB + d, Wb + (size_t)(nBase + row) * KW + kw + c * 4);
        }
    };

    // --- compute one 32-word chunk (R2 loop: popc-sum, IADD3 tree) ----------
    auto compute_stage = [&](int stage) {
        const char* cA = smem + stage * STAGE_B;
        const char* cB = cA + TILE_B;
#pragma unroll
        for (int k = 0; k < KCW; k += 4) {
            uint4 b4[8];
#pragma unroll
            for (int j = 0; j < 8; j++)
                b4[j] = *reinterpret_cast<const uint4*>(
                    cB + (tx + 16 * j) * RSB + k * 4);
#pragma unroll
            for (int i = 0; i < 8; i++) {
                uint4 a4 = *reinterpret_cast<const uint4*>(
                    cA + (ty + 16 * i) * RSB + k * 4);
#pragma unroll
                for (int j = 0; j < 8; j++) {
                    acc[i][j] += __popc(a4.x ^ b4[j].x) + __popc(a4.y ^ b4[j].y)
                               + __popc(a4.z ^ b4[j].z) + __popc(a4.w ^ b4[j].w);
                }
            }
        }
    };

    // --- 2-stage cp.async pipeline ------------------------------------------
    load_stage(0, 0); CP_COMMIT();
    for (int i = 0; i < NCH; i++) {
        if (i + 1 < NCH) load_stage((i + 1) & 1, i + 1);
        CP_COMMIT();
        CP_WAIT(1);
        __syncthreads();
        compute_stage(i & 1);
        __syncthreads();      // buffer (i&1) safe before next overwrite
    }

    // --- epilogue: dot = D - 2*mismatches; pad columns masked ---------------
#pragma unroll
    for (int i = 0; i < 8; i++) {
        int m = mBase + ty + 16 * i;
#pragma unroll
        for (int j = 0; j < 8; j++) {
            int n = nBase + tx + 16 * j;
            if (n < N_DIM)
                out[(size_t)m * N_DIM + n] = (float)(D_DIM - 2 * acc[i][j]);
        }
    }
}

// =============================== launcher ==================================
extern "C" void kernel_launch(void* const* d_in, const int* in_sizes, int n_in,
                              void* d_out, int out_size) {
    const float* inp = (const float*)d_in[0];   // [8192, 12288]
    const float* wt  = (const float*)d_in[1];   // [1000, 12288]
    float* out = (float*)d_out;                 // [8192, 1000]

    uint32_t* bitsA = nullptr;
    uint32_t* bitsW = nullptr;
    cudaGetSymbolAddress((void**)&bitsA, g_bitsA);
    cudaGetSymbolAddress((void**)&bitsW, g_bitsW);

    {   // pack A: 16 words per warp
        int nwords = M_DIM * KW;                // 3,145,728
        int warps  = nwords / 16;
        int blocks = (warps * 32 + 255) / 256;
        pack_sign_A<<<blocks, 256>>>(inp, bitsA, nwords);
    }
    {   // pack W padded to 1024 rows
        int nwords = NP * KW;
        int blocks = (nwords / 4 * 32 + 255) / 256;
        pack_sign_W<<<blocks, 256>>>(wt, bitsW);
    }

    static bool attr_set = false;
    if (!attr_set) {
        cudaFuncSetAttribute(bgemm_popc_kernel,
                             cudaFuncAttributeMaxDynamicSharedMemorySize, SMEM_REQ);
        attr_set = true;
    }
    dim3 grid(NP / 128, M_DIM / 128);   // x = N tiles (A-tile L2 reuse), y = M
    bgemm_popc_kernel<<<grid, 256, SMEM_REQ>>>(bitsA, bitsW, out);
}